// round 7
// baseline (speedup 1.0000x reference)
#include <cuda_runtime.h>

#define BB      16384
#define NSITES  784
#define DD      8
#define OO      10
#define LABEL   392
#define LLEFT   391   // sites 1..391
#define LRIGHT  390   // sites 393..782 (walked reversed, transposed)

typedef unsigned long long u64;

// ---------------- packed f32x2 helpers ----------------
__device__ __forceinline__ u64 pk2(float a, float b) {
    u64 r; asm("mov.b64 %0, {%1, %2};" : "=l"(r) : "f"(a), "f"(b)); return r;
}
__device__ __forceinline__ void upk2(float& a, float& b, u64 r) {
    asm("mov.b64 {%0, %1}, %2;" : "=f"(a), "=f"(b) : "l"(r));
}
__device__ __forceinline__ u64 fma2(u64 a, u64 b, u64 c) {
    u64 d; asm("fma.rn.f32x2 %0, %1, %2, %3;" : "=l"(d) : "l"(a), "l"(b), "l"(c)); return d;
}
__device__ __forceinline__ u64 mul2(u64 a, u64 b) {
    u64 d; asm("mul.rn.f32x2 %0, %1, %2;" : "=l"(d) : "l"(a), "l"(b)); return d;
}

// ---------------- scratch ----------------
// Duplicated-weight tables: per site 256 floats:
//   for i in 0..7: [ (A[i][e],A[i][e]) e=0..7 (16 floats) | (C[i][e],C[i][e]) (16 floats) ]
__device__ __align__(16) float g_WL[LLEFT * 256];
__device__ __align__(16) float g_WR[LRIGHT * 256];
__device__ __align__(8)  float g_Alab[DD * DD * OO];
__device__ __align__(8)  float g_Clab[DD * DD * OO];
__device__ float g_w0c[16];
__device__ float g_wlastc[16];
__device__ __align__(16) float g_vleft[BB * 8];
__device__ __align__(16) float g_u[BB * 8];
__device__ unsigned g_flag[64];

#define P1L 195
#define P2L 196
#define P1R 195
#define P2R 195
#define SW_FLOATS (196 * 256)

// ---------------- weight prep ----------------
__global__ void prep_weights(const float* __restrict__ wl,
                             const float* __restrict__ wlab,
                             const float* __restrict__ wr,
                             const float* __restrict__ w0,
                             const float* __restrict__ wlast) {
    int idx = blockIdx.x * blockDim.x + threadIdx.x;
    if (idx < LLEFT * 128) {
        int s = idx >> 7; int r = idx & 127;
        int i = r >> 4; int h = (r >> 3) & 1; int e = r & 7;
        float a = wl[((s * 8 + i) * 2 + 0) * 8 + e];
        float b = wl[((s * 8 + i) * 2 + 1) * 8 + e];
        float val = h ? (b - a) : a;
        int dst = s * 256 + i * 32 + h * 16 + e * 2;
        g_WL[dst] = val; g_WL[dst + 1] = val;
        return;
    }
    idx -= LLEFT * 128;
    if (idx < LRIGHT * 128) {            // step t uses site_local (389-t), transposed
        int t = idx >> 7; int r = idx & 127;
        int i = r >> 4; int h = (r >> 3) & 1; int e = r & 7;
        int sl = (LRIGHT - 1) - t;
        float a = wr[((sl * 8 + e) * 2 + 0) * 8 + i];
        float b = wr[((sl * 8 + e) * 2 + 1) * 8 + i];
        float val = h ? (b - a) : a;
        int dst = t * 256 + i * 32 + h * 16 + e * 2;
        g_WR[dst] = val; g_WR[dst + 1] = val;
        return;
    }
    idx -= LRIGHT * 128;
    if (idx < DD * DD * OO) {
        int o = idx % OO; int de = idx / OO; int e = de & 7; int d = de >> 3;
        float a = wlab[((d * 2 + 0) * 8 + e) * OO + o];
        float b = wlab[((d * 2 + 1) * 8 + e) * OO + o];
        g_Alab[(d * 8 + e) * OO + o] = a;
        g_Clab[(d * 8 + e) * OO + o] = b - a;
        return;
    }
    idx -= DD * DD * OO;
    if (idx < 8) { g_w0c[idx] = w0[idx]; g_w0c[8 + idx] = w0[8 + idx] - w0[idx]; return; }
    idx -= 8;
    if (idx < 8) {
        g_wlastc[idx]     = wlast[idx * 2 + 0];
        g_wlastc[8 + idx] = wlast[idx * 2 + 1] - wlast[idx * 2 + 0];
        return;
    }
    idx -= 8;
    if (idx < 64) g_flag[idx] = 0;
}

// ---------------- one site step, rows packed in f32x2 lanes ----------------
__device__ __forceinline__ void site_step(const float* __restrict__ wsite,
                                          u64 (&v)[8], u64 pp) {
    const ulonglong2* __restrict__ q = (const ulonglong2*)wsite;
    u64 A[8], C[8];
    {   // i = 0 : init accumulators with mul (2 reads/instr)
        u64 vi = v[0];
        ulonglong2 qa0 = q[0], qa1 = q[1], qa2 = q[2], qa3 = q[3];
        ulonglong2 qc0 = q[4], qc1 = q[5], qc2 = q[6], qc3 = q[7];
        A[0] = mul2(vi, qa0.x); A[1] = mul2(vi, qa0.y);
        A[2] = mul2(vi, qa1.x); A[3] = mul2(vi, qa1.y);
        A[4] = mul2(vi, qa2.x); A[5] = mul2(vi, qa2.y);
        A[6] = mul2(vi, qa3.x); A[7] = mul2(vi, qa3.y);
        C[0] = mul2(vi, qc0.x); C[1] = mul2(vi, qc0.y);
        C[2] = mul2(vi, qc1.x); C[3] = mul2(vi, qc1.y);
        C[4] = mul2(vi, qc2.x); C[5] = mul2(vi, qc2.y);
        C[6] = mul2(vi, qc3.x); C[7] = mul2(vi, qc3.y);
    }
    #pragma unroll
    for (int i = 1; i < 8; i++) {
        u64 vi = v[i];
        ulonglong2 qa0 = q[i*8+0], qa1 = q[i*8+1], qa2 = q[i*8+2], qa3 = q[i*8+3];
        ulonglong2 qc0 = q[i*8+4], qc1 = q[i*8+5], qc2 = q[i*8+6], qc3 = q[i*8+7];
        A[0] = fma2(vi, qa0.x, A[0]); A[1] = fma2(vi, qa0.y, A[1]);
        A[2] = fma2(vi, qa1.x, A[2]); A[3] = fma2(vi, qa1.y, A[3]);
        A[4] = fma2(vi, qa2.x, A[4]); A[5] = fma2(vi, qa2.y, A[5]);
        A[6] = fma2(vi, qa3.x, A[6]); A[7] = fma2(vi, qa3.y, A[7]);
        C[0] = fma2(vi, qc0.x, C[0]); C[1] = fma2(vi, qc0.y, C[1]);
        C[2] = fma2(vi, qc1.x, C[2]); C[3] = fma2(vi, qc1.y, C[3]);
        C[4] = fma2(vi, qc2.x, C[4]); C[5] = fma2(vi, qc2.y, C[5]);
        C[6] = fma2(vi, qc3.x, C[6]); C[7] = fma2(vi, qc3.y, C[7]);
    }
    #pragma unroll
    for (int e = 0; e < 8; e++) v[e] = fma2(pp, C[e], A[e]);
}

// ---------------- label combine for one row ----------------
__device__ __forceinline__ void label_row(const u64* __restrict__ sA,
                                          const u64* __restrict__ sC,
                                          const float (&vl)[8], const float (&uu)[8],
                                          float p, float* __restrict__ out, int row) {
    const u64 p2 = pk2(p, p);
    u64 acc[5] = {0, 0, 0, 0, 0};
    #pragma unroll
    for (int d = 0; d < 8; d++) {
        #pragma unroll
        for (int e = 0; e < 8; e++) {
            const float g = vl[d] * uu[e];
            const u64 g2 = pk2(g, g);
            const u64 gp2 = mul2(g2, p2);
            const int base = (d * 8 + e) * 5;
            #pragma unroll
            for (int k = 0; k < 5; k++) {
                acc[k] = fma2(g2, sA[base + k], acc[k]);
                acc[k] = fma2(gp2, sC[base + k], acc[k]);
            }
        }
    }
    float2* o2 = (float2*)(out + row * OO);
    #pragma unroll
    for (int k = 0; k < 5; k++) {
        float lo, hi; upk2(lo, hi, acc[k]);
        o2[k] = make_float2(lo, hi);
    }
}

__device__ __forceinline__ void stage(float* __restrict__ sw,
                                      const float* __restrict__ gsrc, int n4, int tid) {
    const float4* g4 = (const float4*)gsrc;
    float4* s4 = (float4*)sw;
    for (int i = tid; i < n4; i += 128) s4[i] = g4[i];
}

// ---------------- chain + label kernel ----------------
__global__ __launch_bounds__(128, 1) void chain_kernel(const float* __restrict__ x,
                                                       float* __restrict__ out) {
    extern __shared__ float sw[];
    __shared__ unsigned s_old;
    const int tid = threadIdx.x;
    const int blk = blockIdx.x;            // 0..127
    const bool isLeft = blk < 64;
    const int pair = isLeft ? blk : blk - 64;

    const int r0 = pair * 256 + tid;
    const int r1 = r0 + 128;
    const float* px0 = x + (size_t)r0 * NSITES;
    const float* px1 = x + (size_t)r1 * NSITES;

    u64 v[8];
    if (isLeft) {
        stage(sw, g_WL, P1L * 64, tid);
        __syncthreads();
        float4 f0 = *(const float4*)(px0);
        float4 f1 = *(const float4*)(px1);
        #pragma unroll
        for (int d = 0; d < 8; d++) {
            float c0 = g_w0c[d], c1 = g_w0c[8 + d];
            v[d] = pk2(fmaf(f0.x, c1, c0), fmaf(f1.x, c1, c0));
        }
        float4 n0 = *(const float4*)(px0 + 4);
        float4 n1 = *(const float4*)(px1 + 4);
        site_step(sw + 0 * 256, v, pk2(f0.y, f1.y));   // site 1
        site_step(sw + 1 * 256, v, pk2(f0.z, f1.z));   // site 2
        site_step(sw + 2 * 256, v, pk2(f0.w, f1.w));   // site 3
        const float* wp = sw + 3 * 256;
        #pragma unroll 1
        for (int g = 1; g <= 48; g++) {                // sites 4g..4g+3 (..195)
            f0 = n0; f1 = n1;
            n0 = *(const float4*)(px0 + 4 * g + 4);
            n1 = *(const float4*)(px1 + 4 * g + 4);
            site_step(wp, v, pk2(f0.x, f1.x)); wp += 256;
            site_step(wp, v, pk2(f0.y, f1.y)); wp += 256;
            site_step(wp, v, pk2(f0.z, f1.z)); wp += 256;
            site_step(wp, v, pk2(f0.w, f1.w)); wp += 256;
        }
        __syncthreads();
        stage(sw, g_WL + P1L * 256, P2L * 64, tid);
        __syncthreads();
        wp = sw;
        #pragma unroll 1
        for (int g = 49; g <= 97; g++) {               // sites 196..391
            f0 = n0; f1 = n1;
            n0 = *(const float4*)(px0 + 4 * g + 4);    // g=97 -> x[392..395], valid
            n1 = *(const float4*)(px1 + 4 * g + 4);
            site_step(wp, v, pk2(f0.x, f1.x)); wp += 256;
            site_step(wp, v, pk2(f0.y, f1.y)); wp += 256;
            site_step(wp, v, pk2(f0.z, f1.z)); wp += 256;
            site_step(wp, v, pk2(f0.w, f1.w)); wp += 256;
        }
    } else {
        stage(sw, g_WR, P1R * 64, tid);
        __syncthreads();
        float4 f0 = *(const float4*)(px0 + 780);       // sites 780..783
        float4 f1 = *(const float4*)(px1 + 780);
        #pragma unroll
        for (int d = 0; d < 8; d++) {
            float c0 = g_wlastc[d], c1 = g_wlastc[8 + d];
            v[d] = pk2(fmaf(f0.w, c1, c0), fmaf(f1.w, c1, c0));
        }
        float4 n0 = *(const float4*)(px0 + 776);
        float4 n1 = *(const float4*)(px1 + 776);
        site_step(sw + 0 * 256, v, pk2(f0.z, f1.z));   // site 782
        site_step(sw + 1 * 256, v, pk2(f0.y, f1.y));   // site 781
        site_step(sw + 2 * 256, v, pk2(f0.x, f1.x));   // site 780
        const float* wp = sw + 3 * 256;
        #pragma unroll 1
        for (int m = 0; m < 48; m++) {                 // sites 779-4m .. 776-4m (..588)
            f0 = n0; f1 = n1;
            n0 = *(const float4*)(px0 + 772 - 4 * m);
            n1 = *(const float4*)(px1 + 772 - 4 * m);
            site_step(wp, v, pk2(f0.w, f1.w)); wp += 256;
            site_step(wp, v, pk2(f0.z, f1.z)); wp += 256;
            site_step(wp, v, pk2(f0.y, f1.y)); wp += 256;
            site_step(wp, v, pk2(f0.x, f1.x)); wp += 256;
        }
        __syncthreads();
        stage(sw, g_WR + P1R * 256, P2R * 64, tid);
        __syncthreads();
        wp = sw;
        #pragma unroll 1
        for (int m = 48; m < 96; m++) {                // sites 587..396
            f0 = n0; f1 = n1;
            n0 = *(const float4*)(px0 + 772 - 4 * m);  // m=95 -> x[392..395], valid
            n1 = *(const float4*)(px1 + 772 - 4 * m);
            site_step(wp, v, pk2(f0.w, f1.w)); wp += 256;
            site_step(wp, v, pk2(f0.z, f1.z)); wp += 256;
            site_step(wp, v, pk2(f0.y, f1.y)); wp += 256;
            site_step(wp, v, pk2(f0.x, f1.x)); wp += 256;
        }
        f0 = n0; f1 = n1;                              // x[392..395]: sites 395,394,393
        site_step(wp, v, pk2(f0.w, f1.w)); wp += 256;
        site_step(wp, v, pk2(f0.z, f1.z)); wp += 256;
        site_step(wp, v, pk2(f0.y, f1.y));
    }

    // unpack rows and store side vectors
    {
        float a0[8], a1[8];
        #pragma unroll
        for (int e = 0; e < 8; e++) upk2(a0[e], a1[e], v[e]);
        float* base = isLeft ? g_vleft : g_u;
        float4* d0 = (float4*)(base + r0 * 8);
        d0[0] = make_float4(a0[0], a0[1], a0[2], a0[3]);
        d0[1] = make_float4(a0[4], a0[5], a0[6], a0[7]);
        float4* d1 = (float4*)(base + r1 * 8);
        d1[0] = make_float4(a1[0], a1[1], a1[2], a1[3]);
        d1[1] = make_float4(a1[4], a1[5], a1[6], a1[7]);
    }

    // ---- handoff: second arriver computes the label combine ----
    __threadfence();
    __syncthreads();
    if (tid == 0) s_old = atomicAdd(&g_flag[pair], 1u);
    __syncthreads();
    if (s_old == 0) return;
    __threadfence();

    // stage label weights into SMEM (table region is free now)
    for (int i = tid; i < 640; i += 128) {
        ((u64*)sw)[i]       = ((const u64*)g_Alab)[i];
        ((u64*)sw)[640 + i] = ((const u64*)g_Clab)[i];
    }
    __syncthreads();
    const u64* sA = (const u64*)sw;
    const u64* sC = sA + 640;

    const float* other = isLeft ? g_u : g_vleft;
    float m0[8], m1[8];
    #pragma unroll
    for (int e = 0; e < 8; e++) upk2(m0[e], m1[e], v[e]);

    #pragma unroll 1
    for (int rr = 0; rr < 2; rr++) {
        const int row = rr == 0 ? r0 : r1;
        float* mine = rr == 0 ? m0 : m1;
        float vv[8], oo[8];
        #pragma unroll
        for (int e = 0; e < 8; e++) vv[e] = mine[e];
        const float4* s0 = (const float4*)(other + row * 8);
        float4 a = s0[0], b = s0[1];
        oo[0]=a.x; oo[1]=a.y; oo[2]=a.z; oo[3]=a.w;
        oo[4]=b.x; oo[5]=b.y; oo[6]=b.z; oo[7]=b.w;
        const float pl = x[(size_t)row * NSITES + LABEL];
        if (isLeft) label_row(sA, sC, vv, oo, pl, out, row);
        else        label_row(sA, sC, oo, vv, pl, out, row);
    }
}

// ---------------- launcher ----------------
extern "C" void kernel_launch(void* const* d_in, const int* in_sizes, int n_in,
                              void* d_out, int out_size) {
    const float* x      = (const float*)d_in[0];
    const float* w0     = (const float*)d_in[1];
    const float* Wleft  = (const float*)d_in[2];
    const float* wlabel = (const float*)d_in[3];
    const float* Wright = (const float*)d_in[4];
    const float* wlast  = (const float*)d_in[5];
    float* out = (float*)d_out;

    const int smemBytes = SW_FLOATS * (int)sizeof(float);   // 200704 B
    cudaFuncSetAttribute(chain_kernel, cudaFuncAttributeMaxDynamicSharedMemorySize, smemBytes);

    const int prepN = LLEFT * 128 + LRIGHT * 128 + DD * DD * OO + 8 + 8 + 64;
    prep_weights<<<(prepN + 255) / 256, 256>>>(Wleft, wlabel, Wright, w0, wlast);
    chain_kernel<<<128, 128, smemBytes>>>(x, out);
}

// round 8
// speedup vs baseline: 1.1519x; 1.1519x over previous
#include <cuda_runtime.h>

#define BB      16384
#define NSITES  784
#define DD      8
#define OO      10
#define LABEL   392
#define LLEFT   391   // sites 1..391
#define LRIGHT  390   // sites 393..782 (walked reversed, transposed)
#define NPAIR   74    // CTAs per side
#define SLOTS_PER_CTA 256

typedef unsigned long long u64;

// ---------------- packed f32x2 helpers ----------------
__device__ __forceinline__ u64 pk2(float a, float b) {
    u64 r; asm("mov.b64 %0, {%1, %2};" : "=l"(r) : "f"(a), "f"(b)); return r;
}
__device__ __forceinline__ void upk2(float& a, float& b, u64 r) {
    asm("mov.b64 {%0, %1}, %2;" : "=f"(a), "=f"(b) : "l"(r));
}
__device__ __forceinline__ u64 fma2(u64 a, u64 b, u64 c) {
    u64 d; asm("fma.rn.f32x2 %0, %1, %2, %3;" : "=l"(d) : "l"(a), "l"(b), "l"(c)); return d;
}
__device__ __forceinline__ u64 mul2(u64 a, u64 b) {
    u64 d; asm("mul.rn.f32x2 %0, %1, %2;" : "=l"(d) : "l"(a), "l"(b)); return d;
}

// ---------------- scratch ----------------
__device__ __align__(16) float g_WL[LLEFT * 128];     // per step: A (64) | C (64)
__device__ __align__(16) float g_WR[LRIGHT * 128];    // transposed + reversed
__device__ __align__(8)  float g_Alab[DD * DD * OO];
__device__ __align__(8)  float g_Clab[DD * DD * OO];
__device__ float g_w0c[16];
__device__ float g_wlastc[16];
__device__ __align__(16) float g_vleft[BB * 8];
__device__ __align__(16) float g_u[BB * 8];
__device__ unsigned g_flag[NPAIR];

// ---------------- weight prep ----------------
__global__ void prep_weights(const float* __restrict__ wl,
                             const float* __restrict__ wlab,
                             const float* __restrict__ wr,
                             const float* __restrict__ w0,
                             const float* __restrict__ wlast) {
    int idx = blockIdx.x * blockDim.x + threadIdx.x;
    if (idx < LLEFT * 64) {
        int s = idx >> 6; int r = idx & 63; int d = r >> 3; int e = r & 7;
        float a = wl[((s * 8 + d) * 2 + 0) * 8 + e];
        float b = wl[((s * 8 + d) * 2 + 1) * 8 + e];
        g_WL[s * 128 + d * 8 + e] = a;
        g_WL[s * 128 + 64 + d * 8 + e] = b - a;
        return;
    }
    idx -= LLEFT * 64;
    if (idx < LRIGHT * 64) {           // step t uses site (782 - t), transposed
        int t = idx >> 6; int r = idx & 63; int i = r >> 3; int j = r & 7;
        int site_local = (LRIGHT - 1) - t;
        float a = wr[((site_local * 8 + j) * 2 + 0) * 8 + i];
        float b = wr[((site_local * 8 + j) * 2 + 1) * 8 + i];
        g_WR[t * 128 + i * 8 + j] = a;
        g_WR[t * 128 + 64 + i * 8 + j] = b - a;
        return;
    }
    idx -= LRIGHT * 64;
    if (idx < DD * DD * OO) {
        int o = idx % OO; int de = idx / OO; int e = de & 7; int d = de >> 3;
        float a = wlab[((d * 2 + 0) * 8 + e) * OO + o];
        float b = wlab[((d * 2 + 1) * 8 + e) * OO + o];
        g_Alab[(d * 8 + e) * OO + o] = a;
        g_Clab[(d * 8 + e) * OO + o] = b - a;
        return;
    }
    idx -= DD * DD * OO;
    if (idx < 8) { g_w0c[idx] = w0[idx]; g_w0c[8 + idx] = w0[8 + idx] - w0[idx]; return; }
    idx -= 8;
    if (idx < 8) {
        g_wlastc[idx]     = wlast[idx * 2 + 0];
        g_wlastc[8 + idx] = wlast[idx * 2 + 1] - wlast[idx * 2 + 0];
        return;
    }
    idx -= 8;
    if (idx < NPAIR) g_flag[idx] = 0;
}

// ---------------- one site step, single row (e-packed), mul2-init ----------------
__device__ __forceinline__ void site_step(const float* __restrict__ wsite,
                                          float (&v)[8], float pc) {
    const ulonglong2* __restrict__ w2 = (const ulonglong2*)wsite;
    u64 A0, A1, A2, A3, C0, C1, C2, C3;
    {
        u64 vd = pk2(v[0], v[0]);
        ulonglong2 qa = w2[0], qb = w2[1];
        ulonglong2 qc = w2[16], qd = w2[17];
        A0 = mul2(vd, qa.x); A1 = mul2(vd, qa.y);
        A2 = mul2(vd, qb.x); A3 = mul2(vd, qb.y);
        C0 = mul2(vd, qc.x); C1 = mul2(vd, qc.y);
        C2 = mul2(vd, qd.x); C3 = mul2(vd, qd.y);
    }
    #pragma unroll
    for (int i = 1; i < 8; i++) {
        u64 vd = pk2(v[i], v[i]);
        ulonglong2 qa = w2[2 * i], qb = w2[2 * i + 1];
        ulonglong2 qc = w2[16 + 2 * i], qd = w2[16 + 2 * i + 1];
        A0 = fma2(vd, qa.x, A0); A1 = fma2(vd, qa.y, A1);
        A2 = fma2(vd, qb.x, A2); A3 = fma2(vd, qb.y, A3);
        C0 = fma2(vd, qc.x, C0); C1 = fma2(vd, qc.y, C1);
        C2 = fma2(vd, qd.x, C2); C3 = fma2(vd, qd.y, C3);
    }
    u64 p2 = pk2(pc, pc);
    A0 = fma2(p2, C0, A0); A1 = fma2(p2, C1, A1);
    A2 = fma2(p2, C2, A2); A3 = fma2(p2, C3, A3);
    upk2(v[0], v[1], A0); upk2(v[2], v[3], A1);
    upk2(v[4], v[5], A2); upk2(v[6], v[7], A3);
}

// ---------------- label combine for one row ----------------
__device__ __forceinline__ void label_row(const u64* __restrict__ sA,
                                          const u64* __restrict__ sC,
                                          const float (&vl)[8], const float (&uu)[8],
                                          float p, float* __restrict__ out, int row) {
    const u64 p2 = pk2(p, p);
    u64 acc[5] = {0, 0, 0, 0, 0};
    #pragma unroll
    for (int d = 0; d < 8; d++) {
        #pragma unroll
        for (int e = 0; e < 8; e++) {
            const float g = vl[d] * uu[e];
            const u64 g2 = pk2(g, g);
            const u64 gp2 = mul2(g2, p2);
            const int base = (d * 8 + e) * 5;
            #pragma unroll
            for (int k = 0; k < 5; k++) {
                acc[k] = fma2(g2, sA[base + k], acc[k]);
                acc[k] = fma2(gp2, sC[base + k], acc[k]);
            }
        }
    }
    float2* o2 = (float2*)(out + row * OO);
    #pragma unroll
    for (int k = 0; k < 5; k++) {
        float lo, hi; upk2(lo, hi, acc[k]);
        o2[k] = make_float2(lo, hi);
    }
}

// ---------------- fused chain + label kernel: 148 CTAs, 256 thr, 1 row/thread ----------------
__global__ __launch_bounds__(256, 1) void chain_kernel(const float* __restrict__ x,
                                                       float* __restrict__ out) {
    extern __shared__ float sw[];
    __shared__ unsigned s_old;
    const int tid = threadIdx.x;
    const int blk = blockIdx.x;            // 0..147
    const bool isLeft = blk < NPAIR;
    const int pair = isLeft ? blk : blk - NPAIR;

    {   // stage this side's weights
        const float4* g4 = (const float4*)(isLeft ? g_WL : g_WR);
        float4* s4 = (float4*)sw;
        const int n4 = (isLeft ? LLEFT : LRIGHT) * 32;
        for (int i = tid; i < n4; i += 256) s4[i] = g4[i];
    }
    __syncthreads();

    // slot -> row compression: 74*256 = 18944 slots onto 16384 rows (monotone onto)
    const unsigned slot = pair * SLOTS_PER_CTA + tid;
    const int r = (int)((slot * 32u) / 37u);
    const float* px = x + (size_t)r * NSITES;

    float v[8];
    if (isLeft) {
        float4 f = *(const float4*)(px);
        #pragma unroll
        for (int d = 0; d < 8; d++) v[d] = fmaf(f.x, g_w0c[8 + d], g_w0c[d]);
        float4 nf = *(const float4*)(px + 4);
        site_step(sw + 0 * 128, v, f.y);               // site 1
        site_step(sw + 1 * 128, v, f.z);               // site 2
        site_step(sw + 2 * 128, v, f.w);               // site 3
        const float* wp = sw + 3 * 128;
        #pragma unroll 1
        for (int g = 1; g <= 97; g++) {                // sites 4g..4g+3
            f = nf;
            nf = *(const float4*)(px + 4 * g + 4);     // g=97 -> x[392..395], valid
            site_step(wp, v, f.x); wp += 128;
            site_step(wp, v, f.y); wp += 128;
            site_step(wp, v, f.z); wp += 128;
            site_step(wp, v, f.w); wp += 128;
        }
        float4* d0 = (float4*)(g_vleft + r * 8);
        d0[0] = make_float4(v[0], v[1], v[2], v[3]);
        d0[1] = make_float4(v[4], v[5], v[6], v[7]);
    } else {
        float4 f = *(const float4*)(px + 780);         // sites 780..783
        #pragma unroll
        for (int d = 0; d < 8; d++) v[d] = fmaf(f.w, g_wlastc[8 + d], g_wlastc[d]);
        float4 nf = *(const float4*)(px + 776);
        site_step(sw + 0 * 128, v, f.z);               // site 782
        site_step(sw + 1 * 128, v, f.y);               // site 781
        site_step(sw + 2 * 128, v, f.x);               // site 780
        const float* wp = sw + 3 * 128;
        #pragma unroll 1
        for (int m = 0; m < 96; m++) {                 // sites 779-4m .. 776-4m
            f = nf;
            nf = *(const float4*)(px + 772 - 4 * m);   // m=95 -> x[392..395]; never OOB
            site_step(wp, v, f.w); wp += 128;
            site_step(wp, v, f.z); wp += 128;
            site_step(wp, v, f.y); wp += 128;
            site_step(wp, v, f.x); wp += 128;
        }
        f = nf;                                        // x[392..395]: sites 395,394,393
        site_step(wp, v, f.w); wp += 128;
        site_step(wp, v, f.z); wp += 128;
        site_step(wp, v, f.y);
        float4* d0 = (float4*)(g_u + r * 8);
        d0[0] = make_float4(v[0], v[1], v[2], v[3]);
        d0[1] = make_float4(v[4], v[5], v[6], v[7]);
    }

    // ---- handoff: second arriver of the pair computes the label combine ----
    __threadfence();                                   // release our stores
    __syncthreads();
    if (tid == 0) s_old = atomicAdd(&g_flag[pair], 1u);
    __syncthreads();
    if (s_old == 0) return;                            // first arriver exits
    __threadfence();                                   // acquire other side's stores

    // stage label weights into SMEM (table region is free now)
    for (int i = tid; i < 320; i += 256) {
        ((u64*)sw)[i]       = ((const u64*)g_Alab)[i];
        ((u64*)sw)[320 + i] = ((const u64*)g_Clab)[i];
    }
    __syncthreads();
    const u64* sA = (const u64*)sw;
    const u64* sC = sA + 320;

    const float* other = isLeft ? g_u : g_vleft;
    float oo[8];
    {
        const float4* s0 = (const float4*)(other + r * 8);
        float4 a = s0[0], b = s0[1];
        oo[0]=a.x; oo[1]=a.y; oo[2]=a.z; oo[3]=a.w;
        oo[4]=b.x; oo[5]=b.y; oo[6]=b.z; oo[7]=b.w;
    }
    const float pl = px[LABEL];
    if (isLeft) label_row(sA, sC, v, oo, pl, out, r);
    else        label_row(sA, sC, oo, v, pl, out, r);
}

// ---------------- launcher ----------------
extern "C" void kernel_launch(void* const* d_in, const int* in_sizes, int n_in,
                              void* d_out, int out_size) {
    const float* x      = (const float*)d_in[0];
    const float* w0     = (const float*)d_in[1];
    const float* Wleft  = (const float*)d_in[2];
    const float* wlabel = (const float*)d_in[3];
    const float* Wright = (const float*)d_in[4];
    const float* wlast  = (const float*)d_in[5];
    float* out = (float*)d_out;

    const int chainSmem = LLEFT * 128 * (int)sizeof(float);   // 200192 B
    cudaFuncSetAttribute(chain_kernel, cudaFuncAttributeMaxDynamicSharedMemorySize, chainSmem);

    const int prepN = LLEFT * 64 + LRIGHT * 64 + DD * DD * OO + 8 + 8 + NPAIR;
    prep_weights<<<(prepN + 255) / 256, 256>>>(Wleft, wlabel, Wright, w0, wlast);
    chain_kernel<<<2 * NPAIR, 256, chainSmem>>>(x, out);
}